// round 10
// baseline (speedup 1.0000x reference)
#include <cuda_runtime.h>

#define NN 50000
#define NE 800000
#define DD 96
#define NQ ((NN + 3) / 4)          // 12500 int4 quads
#define SCAN_BLOCKS ((NQ + 255) / 256)   // 49

// ---------------- scratch (device globals; no allocation allowed) ----------
__device__ __align__(16) int   g_cnt [NN];
__device__ __align__(16) int   g_off [NN + 4];
__device__ __align__(16) int   g_fill[NN];
__device__ __align__(16) float g_dinv[NN];
__device__ __align__(16) int   g_bsum[64];
__device__ __align__(16) int2  g_edge[NE];      // .x = src, .y = bits(wn)
__device__ __align__(16) float g_hA [(size_t)NN * DD];
__device__ __align__(16) float g_hB [(size_t)NN * DD];

// ---------------- f32x2 helpers ---------------------------------------------
__device__ __forceinline__ unsigned long long pk2(float x, float y)
{
    unsigned long long r;
    asm("mov.b64 %0, {%1,%2};" : "=l"(r) : "f"(x), "f"(y));
    return r;
}
__device__ __forceinline__ void upk2(unsigned long long v, float& x, float& y)
{
    asm("mov.b64 {%0,%1}, %2;" : "=f"(x), "=f"(y) : "l"(v));
}
__device__ __forceinline__ void ffma2(unsigned long long& d,
                                      unsigned long long a,
                                      unsigned long long b)
{
    asm("fma.rn.f32x2 %0, %1, %2, %0;" : "+l"(d) : "l"(a), "l"(b));
}

// ---------------- graph preprocessing --------------------------------------
__global__ void k_zero()
{
    int i = blockIdx.x * blockDim.x + threadIdx.x;
    if (i < NQ) ((int4*)g_cnt)[i] = make_int4(0, 0, 0, 0);
}

// 1 edge/thread: scatter atomics want max thread-parallelism (measured).
__global__ void k_hist(const int* __restrict__ dst)
{
    int e = blockIdx.x * blockDim.x + threadIdx.x;
    if (e < NE) atomicAdd(&g_cnt[dst[e]], 1);
}

// ---- multi-block exclusive scan, phase 1: per-block scan + block totals ----
__global__ void k_scan1()
{
    __shared__ int wsum[8];
    int tid = threadIdx.x, lane = tid & 31, wid = tid >> 5;
    int qi = blockIdx.x * 256 + tid;

    int4 v = make_int4(0, 0, 0, 0);
    if (qi < NQ) v = ((const int4*)g_cnt)[qi];
    int t0 = v.x, t1 = t0 + v.y, t2 = t1 + v.z, t3 = t2 + v.w;

    int inc = t3;
    #pragma unroll
    for (int d = 1; d < 32; d <<= 1) {
        int t = __shfl_up_sync(0xffffffffu, inc, d);
        if (lane >= d) inc += t;
    }
    if (lane == 31) wsum[wid] = inc;
    __syncthreads();
    if (wid == 0 && lane < 8) {
        int w = wsum[lane];
        int wi = w;
        #pragma unroll
        for (int d = 1; d < 8; d <<= 1) {
            int t = __shfl_up_sync(0x000000ffu, wi, d);
            if (lane >= d) wi += t;
        }
        wsum[lane] = wi - w;       // exclusive prefix of warp sums
    }
    __syncthreads();

    int excl = wsum[wid] + inc - t3;   // block-local exclusive prefix
    if (qi < NQ) {
        ((int4*)g_off)[qi] = make_int4(excl, excl + t0, excl + t1, excl + t2);
        ((float4*)g_dinv)[qi] = make_float4(rsqrtf((float)(v.x + 1)),
                                            rsqrtf((float)(v.y + 1)),
                                            rsqrtf((float)(v.z + 1)),
                                            rsqrtf((float)(v.w + 1)));
    }
    if (tid == 255) g_bsum[blockIdx.x] = wsum[wid] + inc;   // block total
}

// phase 2: exclusive scan of SCAN_BLOCKS (<=64) block totals
__global__ void k_scan2()
{
    __shared__ int w0tot;
    int tid = threadIdx.x;
    int v = (tid < SCAN_BLOCKS) ? g_bsum[tid] : 0;
    int inc = v;
    int lane = tid & 31;
    #pragma unroll
    for (int d = 1; d < 32; d <<= 1) {
        int t = __shfl_up_sync(0xffffffffu, inc, d);
        if (lane >= d) inc += t;
    }
    if (tid == 31) w0tot = inc;
    __syncthreads();
    int excl = inc - v + ((tid >= 32) ? w0tot : 0);
    if (tid < SCAN_BLOCKS) g_bsum[tid] = excl;
}

// phase 3: add block offsets, produce final g_off + g_fill
__global__ void k_scan3()
{
    int tid = threadIdx.x;
    int qi = blockIdx.x * 256 + tid;
    if (qi < NQ) {
        int add = g_bsum[blockIdx.x];
        int4 o = ((int4*)g_off)[qi];
        o.x += add; o.y += add; o.z += add; o.w += add;
        ((int4*)g_off)[qi]  = o;
        ((int4*)g_fill)[qi] = o;
    }
    if (blockIdx.x == 0 && tid == 0) g_off[NN] = NE;   // total = NE
}

// 1 edge/thread (measured best).
__global__ void k_fill(const int* __restrict__ src,
                       const int* __restrict__ dst)
{
    int e = blockIdx.x * blockDim.x + threadIdx.x;
    if (e < NE) {
        int s = src[e];
        int d = dst[e];
        int p = atomicAdd(&g_fill[d], 1);
        g_edge[p] = make_int2(s, __float_as_int(g_dinv[s] * g_dinv[d]));
    }
}

// ---------------- GEMM: g_hA = Xin @ W  (Xin: [NN,96], W: [96,96]) ---------
__global__ __launch_bounds__(384) void k_gemm(const float* __restrict__ Xext,
                                              const float* __restrict__ W)
{
    __shared__ float Ws[96 * 96];
    __shared__ float Xs[96 * 64];
    int tid = threadIdx.x;

    const float* X = Xext ? Xext : g_hB;

    const float4* W4  = (const float4*)W;
    float4*       Ws4 = (float4*)Ws;
    #pragma unroll
    for (int i = 0; i < 6; i++) Ws4[tid + i * 384] = W4[tid + i * 384];

    int row0 = blockIdx.x * 64;
    #pragma unroll
    for (int i = 0; i < 4; i++) {
        int idx = tid + i * 384;        // 0..1535 -> (m, q)
        int m = idx / 24, q = idx % 24;
        int row = row0 + m;
        float4 v = make_float4(0.f, 0.f, 0.f, 0.f);
        if (row < NN) v = ((const float4*)(X + (size_t)row * 96))[q];
        Xs[(q * 4 + 0) * 64 + m] = v.x;
        Xs[(q * 4 + 1) * 64 + m] = v.y;
        Xs[(q * 4 + 2) * 64 + m] = v.z;
        Xs[(q * 4 + 3) * 64 + m] = v.w;
    }
    __syncthreads();

    int tn = tid % 24;      // 4-col group
    int tm = tid / 24;      // 4-row group

    unsigned long long acc[4][2];
    unsigned long long z = pk2(0.f, 0.f);
    #pragma unroll
    for (int i = 0; i < 4; i++) { acc[i][0] = z; acc[i][1] = z; }

    #pragma unroll 4
    for (int k = 0; k < 96; k++) {
        float4 a4 = *(const float4*)&Xs[k * 64 + tm * 4];
        float4 b4 = *(const float4*)&Ws[k * 96 + tn * 4];
        unsigned long long b01 = pk2(b4.x, b4.y);
        unsigned long long b23 = pk2(b4.z, b4.w);
        unsigned long long aa;
        aa = pk2(a4.x, a4.x); ffma2(acc[0][0], aa, b01); ffma2(acc[0][1], aa, b23);
        aa = pk2(a4.y, a4.y); ffma2(acc[1][0], aa, b01); ffma2(acc[1][1], aa, b23);
        aa = pk2(a4.z, a4.z); ffma2(acc[2][0], aa, b01); ffma2(acc[2][1], aa, b23);
        aa = pk2(a4.w, a4.w); ffma2(acc[3][0], aa, b01); ffma2(acc[3][1], aa, b23);
    }

    #pragma unroll
    for (int i = 0; i < 4; i++) {
        int row = row0 + tm * 4 + i;
        if (row < NN) {
            float r0, r1, r2, r3;
            upk2(acc[i][0], r0, r1);
            upk2(acc[i][1], r2, r3);
            *(float4*)&g_hA[(size_t)row * 96 + tn * 4] = make_float4(r0, r1, r2, r3);
        }
    }
}

// ---------------- aggregation core (one warp per node) ---------------------
// Lane<24 owns one float4 of the 96-float row: 1 LDG.128 per edge (vs 3
// LDG.32) at identical sector count — cuts load-issue 3x. All fp32.
__device__ __forceinline__ void agg_node(int node, int lane, bool act,
                                         const float* __restrict__ bias,
                                         float4& a)
{
    const float4* H4 = (const float4*)g_hA;

    float di = g_dinv[node];
    float wself = di * di;
    float4 hs = make_float4(0.f, 0.f, 0.f, 0.f);
    if (act) hs = H4[(size_t)node * 24 + lane];
    a.x = wself * hs.x; a.y = wself * hs.y; a.z = wself * hs.z; a.w = wself * hs.w;

    int j  = g_off[node];
    int e1 = g_off[node + 1];

    for (; j + 3 < e1; j += 4) {
        int2 eA = g_edge[j];
        int2 eB = g_edge[j + 1];
        int2 eC = g_edge[j + 2];
        int2 eD = g_edge[j + 3];
        float4 vA = make_float4(0.f,0.f,0.f,0.f), vB = vA, vC = vA, vD = vA;
        if (act) {
            vA = H4[(size_t)eA.x * 24 + lane];
            vB = H4[(size_t)eB.x * 24 + lane];
            vC = H4[(size_t)eC.x * 24 + lane];
            vD = H4[(size_t)eD.x * 24 + lane];
        }
        float wA = __int_as_float(eA.y);
        float wB = __int_as_float(eB.y);
        float wC = __int_as_float(eC.y);
        float wD = __int_as_float(eD.y);
        a.x += wA * vA.x; a.y += wA * vA.y; a.z += wA * vA.z; a.w += wA * vA.w;
        a.x += wB * vB.x; a.y += wB * vB.y; a.z += wB * vB.z; a.w += wB * vB.w;
        a.x += wC * vC.x; a.y += wC * vC.y; a.z += wC * vC.z; a.w += wC * vC.w;
        a.x += wD * vD.x; a.y += wD * vD.y; a.z += wD * vD.z; a.w += wD * vD.w;
    }
    for (; j < e1; j++) {
        int2 eA = g_edge[j];
        float4 vA = make_float4(0.f,0.f,0.f,0.f);
        if (act) vA = H4[(size_t)eA.x * 24 + lane];
        float wA = __int_as_float(eA.y);
        a.x += wA * vA.x; a.y += wA * vA.y; a.z += wA * vA.z; a.w += wA * vA.w;
    }
    if (act) {
        float4 b4 = ((const float4*)bias)[lane];
        a.x = fmaxf(a.x + b4.x, 0.f);
        a.y = fmaxf(a.y + b4.y, 0.f);
        a.z = fmaxf(a.z + b4.z, 0.f);
        a.w = fmaxf(a.w + b4.w, 0.f);
    }
}

// layers 0,1: g_hB = relu(A_hat @ g_hA + b)
__global__ __launch_bounds__(256) void k_agg(const float* __restrict__ bias)
{
    int node = blockIdx.x * 8 + threadIdx.y;
    if (node >= NN) return;
    int lane = threadIdx.x;
    bool act = lane < 24;

    float4 a;
    agg_node(node, lane, act, bias, a);

    if (act) ((float4*)g_hB)[(size_t)node * 24 + lane] = a;
}

// layer 2 + FC head fused: out = relu(A_hat @ g_hA + b2) @ Wfc + bfc
__global__ __launch_bounds__(256) void k_agg_fc(const float* __restrict__ bias,
                                                const float* __restrict__ Wfc,
                                                const float* __restrict__ bfc,
                                                float* __restrict__ Out)
{
    int node = blockIdx.x * 8 + threadIdx.y;
    if (node >= NN) return;
    int lane = threadIdx.x;
    bool act = lane < 24;

    float4 a;
    agg_node(node, lane, act, bias, a);

    float o0 = 0.f, o1 = 0.f, o2 = 0.f, o3 = 0.f;
    if (act) {
        const float4* W4 = (const float4*)Wfc;     // 96 rows of float4
        float4 w0 = W4[lane * 4 + 0];
        float4 w1 = W4[lane * 4 + 1];
        float4 w2 = W4[lane * 4 + 2];
        float4 w3 = W4[lane * 4 + 3];
        o0 = a.x * w0.x + a.y * w1.x + a.z * w2.x + a.w * w3.x;
        o1 = a.x * w0.y + a.y * w1.y + a.z * w2.y + a.w * w3.y;
        o2 = a.x * w0.z + a.y * w1.z + a.z * w2.z + a.w * w3.z;
        o3 = a.x * w0.w + a.y * w1.w + a.z * w2.w + a.w * w3.w;
    }

    #pragma unroll
    for (int d = 16; d > 0; d >>= 1) {
        o0 += __shfl_xor_sync(0xffffffffu, o0, d);
        o1 += __shfl_xor_sync(0xffffffffu, o1, d);
        o2 += __shfl_xor_sync(0xffffffffu, o2, d);
        o3 += __shfl_xor_sync(0xffffffffu, o3, d);
    }
    if (lane == 0) {
        const float4 bf = *(const float4*)bfc;
        *(float4*)&Out[(size_t)node * 4] =
            make_float4(o0 + bf.x, o1 + bf.y, o2 + bf.z, o3 + bf.w);
    }
}

// ---------------- launch ----------------------------------------------------
extern "C" void kernel_launch(void* const* d_in, const int* in_sizes, int n_in,
                              void* d_out, int out_size)
{
    const float* x    = (const float*)d_in[0];
    const int*   ei   = (const int*)d_in[1];     // int32, [2, NE]
    const float* W0   = (const float*)d_in[2];
    const float* b0   = (const float*)d_in[3];
    const float* W1   = (const float*)d_in[4];
    const float* b1   = (const float*)d_in[5];
    const float* W2   = (const float*)d_in[6];
    const float* b2   = (const float*)d_in[7];
    const float* Wfc  = (const float*)d_in[8];
    const float* bfc  = (const float*)d_in[9];
    float*       out  = (float*)d_out;

    const int* srcE = ei;
    const int* dstE = ei + NE;

    // one-time resources (no device memory; work per call is identical)
    static cudaStream_t s2 = nullptr;
    static cudaEvent_t ev_fork = nullptr, ev_join = nullptr;
    if (!s2) {
        cudaStreamCreateWithFlags(&s2, cudaStreamNonBlocking);
        cudaEventCreateWithFlags(&ev_fork, cudaEventDisableTiming);
        cudaEventCreateWithFlags(&ev_join, cudaEventDisableTiming);
    }

    int gb_zero = (NQ + 255) / 256;
    int gb_e    = (NE + 255) / 256;
    int gemm_blocks = (NN + 63) / 64;
    dim3 agg_block(32, 8);
    int agg_blocks = (NN + 7) / 8;

    // fork: gemm0 (x @ W0 -> hA) runs concurrently with graph preprocessing
    cudaEventRecord(ev_fork, 0);
    cudaStreamWaitEvent(s2, ev_fork, 0);
    k_gemm<<<gemm_blocks, 384, 0, s2>>>(x, W0);
    cudaEventRecord(ev_join, s2);

    // main stream: graph preprocessing chain
    k_zero <<<gb_zero, 256>>>();
    k_hist <<<gb_e, 256>>>(dstE);
    k_scan1<<<SCAN_BLOCKS, 256>>>();
    k_scan2<<<1, 64>>>();
    k_scan3<<<SCAN_BLOCKS, 256>>>();
    k_fill <<<gb_e, 256>>>(srcE, dstE);

    // join: agg0 needs both hA (gemm0) and the CSR
    cudaStreamWaitEvent(0, ev_join, 0);
    k_agg<<<agg_blocks, agg_block>>>(b0);

    // layer 1
    k_gemm<<<gemm_blocks, 384>>>(nullptr, W1);
    k_agg <<<agg_blocks, agg_block>>>(b1);
    // layer 2 + FC head fused
    k_gemm<<<gemm_blocks, 384>>>(nullptr, W2);
    k_agg_fc<<<agg_blocks, agg_block>>>(b2, Wfc, bfc, out);

    (void)in_sizes; (void)n_in; (void)out_size;
}

// round 11
// speedup vs baseline: 1.6884x; 1.6884x over previous
#include <cuda_runtime.h>

#define NN 50000
#define NE 800000
#define DD 96
#define NQ ((NN + 3) / 4)          // 12500 int4 quads
#define SCAN_BLOCKS ((NQ + 255) / 256)   // 49

// ---------------- scratch (device globals; no allocation allowed) ----------
__device__ __align__(16) int   g_cnt [NN];
__device__ __align__(16) int   g_off [NN + 4];
__device__ __align__(16) float g_dinv[NN];
__device__ __align__(16) int   g_bsum[64];
__device__ __align__(16) int   g_epos[NE];      // edge position within dst bucket
__device__ __align__(16) int2  g_edge[NE];      // .x = src, .y = bits(wn)
__device__ __align__(16) float g_hA [(size_t)NN * DD];
__device__ __align__(16) float g_hB [(size_t)NN * DD];

// ---------------- f32x2 helpers ---------------------------------------------
__device__ __forceinline__ unsigned long long pk2(float x, float y)
{
    unsigned long long r;
    asm("mov.b64 %0, {%1,%2};" : "=l"(r) : "f"(x), "f"(y));
    return r;
}
__device__ __forceinline__ void upk2(unsigned long long v, float& x, float& y)
{
    asm("mov.b64 {%0,%1}, %2;" : "=f"(x), "=f"(y) : "l"(v));
}
__device__ __forceinline__ void ffma2(unsigned long long& d,
                                      unsigned long long a,
                                      unsigned long long b)
{
    asm("fma.rn.f32x2 %0, %1, %2, %0;" : "+l"(d) : "l"(a), "l"(b));
}

// ---------------- graph preprocessing --------------------------------------
__global__ void k_zero()
{
    int i = blockIdx.x * blockDim.x + threadIdx.x;
    if (i < NQ) ((int4*)g_cnt)[i] = make_int4(0, 0, 0, 0);
}

// 1 edge/thread; also records this edge's rank within its dst bucket so
// k_fill needs no atomic.
__global__ void k_hist(const int* __restrict__ dst)
{
    int e = blockIdx.x * blockDim.x + threadIdx.x;
    if (e < NE) {
        int p = atomicAdd(&g_cnt[dst[e]], 1);
        g_epos[e] = p;
    }
}

// ---- multi-block exclusive scan, phase 1: per-block scan + block totals ----
__global__ void k_scan1()
{
    __shared__ int wsum[8];
    int tid = threadIdx.x, lane = tid & 31, wid = tid >> 5;
    int qi = blockIdx.x * 256 + tid;

    int4 v = make_int4(0, 0, 0, 0);
    if (qi < NQ) v = ((const int4*)g_cnt)[qi];
    int t0 = v.x, t1 = t0 + v.y, t2 = t1 + v.z, t3 = t2 + v.w;

    int inc = t3;
    #pragma unroll
    for (int d = 1; d < 32; d <<= 1) {
        int t = __shfl_up_sync(0xffffffffu, inc, d);
        if (lane >= d) inc += t;
    }
    if (lane == 31) wsum[wid] = inc;
    __syncthreads();
    if (wid == 0 && lane < 8) {
        int w = wsum[lane];
        int wi = w;
        #pragma unroll
        for (int d = 1; d < 8; d <<= 1) {
            int t = __shfl_up_sync(0x000000ffu, wi, d);
            if (lane >= d) wi += t;
        }
        wsum[lane] = wi - w;       // exclusive prefix of warp sums
    }
    __syncthreads();

    int excl = wsum[wid] + inc - t3;   // block-local exclusive prefix
    if (qi < NQ) {
        ((int4*)g_off)[qi] = make_int4(excl, excl + t0, excl + t1, excl + t2);
        ((float4*)g_dinv)[qi] = make_float4(rsqrtf((float)(v.x + 1)),
                                            rsqrtf((float)(v.y + 1)),
                                            rsqrtf((float)(v.z + 1)),
                                            rsqrtf((float)(v.w + 1)));
    }
    if (tid == 255) g_bsum[blockIdx.x] = wsum[wid] + inc;   // block total
}

// phase 2: exclusive scan of SCAN_BLOCKS (<=64) block totals
__global__ void k_scan2()
{
    __shared__ int w0tot;
    int tid = threadIdx.x;
    int v = (tid < SCAN_BLOCKS) ? g_bsum[tid] : 0;
    int inc = v;
    int lane = tid & 31;
    #pragma unroll
    for (int d = 1; d < 32; d <<= 1) {
        int t = __shfl_up_sync(0xffffffffu, inc, d);
        if (lane >= d) inc += t;
    }
    if (tid == 31) w0tot = inc;
    __syncthreads();
    int excl = inc - v + ((tid >= 32) ? w0tot : 0);
    if (tid < SCAN_BLOCKS) g_bsum[tid] = excl;
}

// phase 3: add block offsets, produce final g_off
__global__ void k_scan3()
{
    int tid = threadIdx.x;
    int qi = blockIdx.x * 256 + tid;
    if (qi < NQ) {
        int add = g_bsum[blockIdx.x];
        int4 o = ((int4*)g_off)[qi];
        o.x += add; o.y += add; o.z += add; o.w += add;
        ((int4*)g_off)[qi] = o;
    }
    if (blockIdx.x == 0 && tid == 0) g_off[NN] = NE;   // total = NE
}

// 1 edge/thread, atomic-free: slot = g_off[dst] + g_epos[e].
__global__ void k_fill(const int* __restrict__ src,
                       const int* __restrict__ dst)
{
    int e = blockIdx.x * blockDim.x + threadIdx.x;
    if (e < NE) {
        int s = src[e];
        int d = dst[e];
        int p = g_off[d] + g_epos[e];
        g_edge[p] = make_int2(s, __float_as_int(g_dinv[s] * g_dinv[d]));
    }
}

// ---------------- GEMM: g_hA = Xin @ W  (Xin: [NN,96], W: [96,96]) ---------
__global__ __launch_bounds__(384) void k_gemm(const float* __restrict__ Xext,
                                              const float* __restrict__ W)
{
    __shared__ float Ws[96 * 96];
    __shared__ float Xs[96 * 64];
    int tid = threadIdx.x;

    const float* X = Xext ? Xext : g_hB;

    const float4* W4  = (const float4*)W;
    float4*       Ws4 = (float4*)Ws;
    #pragma unroll
    for (int i = 0; i < 6; i++) Ws4[tid + i * 384] = W4[tid + i * 384];

    int row0 = blockIdx.x * 64;
    #pragma unroll
    for (int i = 0; i < 4; i++) {
        int idx = tid + i * 384;        // 0..1535 -> (m, q)
        int m = idx / 24, q = idx % 24;
        int row = row0 + m;
        float4 v = make_float4(0.f, 0.f, 0.f, 0.f);
        if (row < NN) v = ((const float4*)(X + (size_t)row * 96))[q];
        Xs[(q * 4 + 0) * 64 + m] = v.x;
        Xs[(q * 4 + 1) * 64 + m] = v.y;
        Xs[(q * 4 + 2) * 64 + m] = v.z;
        Xs[(q * 4 + 3) * 64 + m] = v.w;
    }
    __syncthreads();

    int tn = tid % 24;      // 4-col group
    int tm = tid / 24;      // 4-row group

    unsigned long long acc[4][2];
    unsigned long long z = pk2(0.f, 0.f);
    #pragma unroll
    for (int i = 0; i < 4; i++) { acc[i][0] = z; acc[i][1] = z; }

    #pragma unroll 4
    for (int k = 0; k < 96; k++) {
        float4 a4 = *(const float4*)&Xs[k * 64 + tm * 4];
        float4 b4 = *(const float4*)&Ws[k * 96 + tn * 4];
        unsigned long long b01 = pk2(b4.x, b4.y);
        unsigned long long b23 = pk2(b4.z, b4.w);
        unsigned long long aa;
        aa = pk2(a4.x, a4.x); ffma2(acc[0][0], aa, b01); ffma2(acc[0][1], aa, b23);
        aa = pk2(a4.y, a4.y); ffma2(acc[1][0], aa, b01); ffma2(acc[1][1], aa, b23);
        aa = pk2(a4.z, a4.z); ffma2(acc[2][0], aa, b01); ffma2(acc[2][1], aa, b23);
        aa = pk2(a4.w, a4.w); ffma2(acc[3][0], aa, b01); ffma2(acc[3][1], aa, b23);
    }

    #pragma unroll
    for (int i = 0; i < 4; i++) {
        int row = row0 + tm * 4 + i;
        if (row < NN) {
            float r0, r1, r2, r3;
            upk2(acc[i][0], r0, r1);
            upk2(acc[i][1], r2, r3);
            *(float4*)&g_hA[(size_t)row * 96 + tn * 4] = make_float4(r0, r1, r2, r3);
        }
    }
}

// ---------------- aggregation core (one warp per node, R5/R9 shape) --------
__device__ __forceinline__ void agg_node(int node, int lane,
                                         const float* __restrict__ bias,
                                         float& a0, float& a1, float& a2)
{
    const float* H = g_hA;

    float di = g_dinv[node];
    float wself = di * di;
    const float* hr = H + (size_t)node * 96;
    a0 = wself * hr[lane];
    a1 = wself * hr[lane + 32];
    a2 = wself * hr[lane + 64];

    int j  = g_off[node];
    int e1 = g_off[node + 1];

    for (; j + 3 < e1; j += 4) {
        int2 eA = g_edge[j];
        int2 eB = g_edge[j + 1];
        int2 eC = g_edge[j + 2];
        int2 eD = g_edge[j + 3];
        const float* ha = H + (size_t)eA.x * 96;
        const float* hb = H + (size_t)eB.x * 96;
        const float* hc = H + (size_t)eC.x * 96;
        const float* hd = H + (size_t)eD.x * 96;
        float wA = __int_as_float(eA.y);
        float wB = __int_as_float(eB.y);
        float wC = __int_as_float(eC.y);
        float wD = __int_as_float(eD.y);
        float vA0 = ha[lane], vA1 = ha[lane + 32], vA2 = ha[lane + 64];
        float vB0 = hb[lane], vB1 = hb[lane + 32], vB2 = hb[lane + 64];
        float vC0 = hc[lane], vC1 = hc[lane + 32], vC2 = hc[lane + 64];
        float vD0 = hd[lane], vD1 = hd[lane + 32], vD2 = hd[lane + 64];
        a0 += wA * vA0; a1 += wA * vA1; a2 += wA * vA2;
        a0 += wB * vB0; a1 += wB * vB1; a2 += wB * vB2;
        a0 += wC * vC0; a1 += wC * vC1; a2 += wC * vC2;
        a0 += wD * vD0; a1 += wD * vD1; a2 += wD * vD2;
    }
    for (; j < e1; j++) {
        int2 eA = g_edge[j];
        const float* ha = H + (size_t)eA.x * 96;
        float wA = __int_as_float(eA.y);
        a0 += wA * ha[lane];
        a1 += wA * ha[lane + 32];
        a2 += wA * ha[lane + 64];
    }
    a0 = fmaxf(a0 + bias[lane],      0.f);
    a1 = fmaxf(a1 + bias[lane + 32], 0.f);
    a2 = fmaxf(a2 + bias[lane + 64], 0.f);
}

// layers 0,1: g_hB = relu(A_hat @ g_hA + b)
__global__ __launch_bounds__(256) void k_agg(const float* __restrict__ bias)
{
    int node = blockIdx.x * 8 + threadIdx.y;
    if (node >= NN) return;
    int lane = threadIdx.x;

    float a0, a1, a2;
    agg_node(node, lane, bias, a0, a1, a2);

    size_t o = (size_t)node * 96 + lane;
    g_hB[o]      = a0;
    g_hB[o + 32] = a1;
    g_hB[o + 64] = a2;
}

// layer 2 + FC head fused: out = relu(A_hat @ g_hA + b2) @ Wfc + bfc
__global__ __launch_bounds__(256) void k_agg_fc(const float* __restrict__ bias,
                                                const float* __restrict__ Wfc,
                                                const float* __restrict__ bfc,
                                                float* __restrict__ Out)
{
    int node = blockIdx.x * 8 + threadIdx.y;
    if (node >= NN) return;
    int lane = threadIdx.x;

    float a0, a1, a2;
    agg_node(node, lane, bias, a0, a1, a2);

    const float4* W4 = (const float4*)Wfc;         // [96] rows of float4
    float4 w0 = W4[lane];
    float4 w1 = W4[lane + 32];
    float4 w2 = W4[lane + 64];

    float o0 = a0 * w0.x + a1 * w1.x + a2 * w2.x;
    float o1 = a0 * w0.y + a1 * w1.y + a2 * w2.y;
    float o2 = a0 * w0.z + a1 * w1.z + a2 * w2.z;
    float o3 = a0 * w0.w + a1 * w1.w + a2 * w2.w;

    #pragma unroll
    for (int d = 16; d > 0; d >>= 1) {
        o0 += __shfl_xor_sync(0xffffffffu, o0, d);
        o1 += __shfl_xor_sync(0xffffffffu, o1, d);
        o2 += __shfl_xor_sync(0xffffffffu, o2, d);
        o3 += __shfl_xor_sync(0xffffffffu, o3, d);
    }
    if (lane == 0) {
        const float4 bf = *(const float4*)bfc;
        *(float4*)&Out[(size_t)node * 4] =
            make_float4(o0 + bf.x, o1 + bf.y, o2 + bf.z, o3 + bf.w);
    }
}

// ---------------- launch ----------------------------------------------------
extern "C" void kernel_launch(void* const* d_in, const int* in_sizes, int n_in,
                              void* d_out, int out_size)
{
    const float* x    = (const float*)d_in[0];
    const int*   ei   = (const int*)d_in[1];     // int32, [2, NE]
    const float* W0   = (const float*)d_in[2];
    const float* b0   = (const float*)d_in[3];
    const float* W1   = (const float*)d_in[4];
    const float* b1   = (const float*)d_in[5];
    const float* W2   = (const float*)d_in[6];
    const float* b2   = (const float*)d_in[7];
    const float* Wfc  = (const float*)d_in[8];
    const float* bfc  = (const float*)d_in[9];
    float*       out  = (float*)d_out;

    const int* srcE = ei;
    const int* dstE = ei + NE;

    // one-time resources (no device memory; work per call is identical)
    static cudaStream_t s2 = nullptr;
    static cudaEvent_t ev_fork = nullptr, ev_join = nullptr;
    if (!s2) {
        cudaStreamCreateWithFlags(&s2, cudaStreamNonBlocking);
        cudaEventCreateWithFlags(&ev_fork, cudaEventDisableTiming);
        cudaEventCreateWithFlags(&ev_join, cudaEventDisableTiming);
    }

    int gb_zero = (NQ + 255) / 256;
    int gb_e    = (NE + 255) / 256;
    int gemm_blocks = (NN + 63) / 64;
    dim3 agg_block(32, 8);
    int agg_blocks = (NN + 7) / 8;

    // fork: gemm0 (x @ W0 -> hA) runs concurrently with graph preprocessing
    cudaEventRecord(ev_fork, 0);
    cudaStreamWaitEvent(s2, ev_fork, 0);
    k_gemm<<<gemm_blocks, 384, 0, s2>>>(x, W0);
    cudaEventRecord(ev_join, s2);

    // main stream: graph preprocessing chain
    k_zero <<<gb_zero, 256>>>();
    k_hist <<<gb_e, 256>>>(dstE);
    k_scan1<<<SCAN_BLOCKS, 256>>>();
    k_scan2<<<1, 64>>>();
    k_scan3<<<SCAN_BLOCKS, 256>>>();
    k_fill <<<gb_e, 256>>>(srcE, dstE);

    // join: agg0 needs both hA (gemm0) and the CSR
    cudaStreamWaitEvent(0, ev_join, 0);
    k_agg<<<agg_blocks, agg_block>>>(b0);

    // layer 1
    k_gemm<<<gemm_blocks, 384>>>(nullptr, W1);
    k_agg <<<agg_blocks, agg_block>>>(b1);
    // layer 2 + FC head fused
    k_gemm<<<gemm_blocks, 384>>>(nullptr, W2);
    k_agg_fc<<<agg_blocks, agg_block>>>(b2, Wfc, bfc, out);

    (void)in_sizes; (void)n_in; (void)out_size;
}

// round 12
// speedup vs baseline: 1.7057x; 1.0103x over previous
#include <cuda_runtime.h>

#define NN 50000
#define NE 800000
#define DD 96
#define NQ ((NN + 3) / 4)          // 12500 int4 quads
#define SCAN_BLOCKS ((NQ + 255) / 256)   // 49

// ---------------- scratch (device globals; no allocation allowed) ----------
__device__ __align__(16) int   g_cnt [NN];
__device__ __align__(16) int   g_off [NN + 4];
__device__ __align__(16) float g_dinv[NN];
__device__ __align__(16) int   g_bsum[64];
__device__ __align__(16) int   g_epos[NE];      // edge position within dst bucket
__device__ __align__(16) int2  g_edge[NE];      // .x = src, .y = bits(wn)
__device__ __align__(16) float g_hA [(size_t)NN * DD];
__device__ __align__(16) float g_hB [(size_t)NN * DD];

// ---------------- f32x2 helpers ---------------------------------------------
__device__ __forceinline__ unsigned long long pk2(float x, float y)
{
    unsigned long long r;
    asm("mov.b64 %0, {%1,%2};" : "=l"(r) : "f"(x), "f"(y));
    return r;
}
__device__ __forceinline__ void upk2(unsigned long long v, float& x, float& y)
{
    asm("mov.b64 {%0,%1}, %2;" : "=f"(x), "=f"(y) : "l"(v));
}
__device__ __forceinline__ void ffma2(unsigned long long& d,
                                      unsigned long long a,
                                      unsigned long long b)
{
    asm("fma.rn.f32x2 %0, %1, %2, %0;" : "+l"(d) : "l"(a), "l"(b));
}

// ---------------- graph preprocessing --------------------------------------
__global__ void k_zero()
{
    int i = blockIdx.x * blockDim.x + threadIdx.x;
    if (i < NQ) ((int4*)g_cnt)[i] = make_int4(0, 0, 0, 0);
}

// 1 edge/thread; also records this edge's rank within its dst bucket so
// k_fill needs no atomic.
__global__ void k_hist(const int* __restrict__ dst)
{
    int e = blockIdx.x * blockDim.x + threadIdx.x;
    if (e < NE) {
        int p = atomicAdd(&g_cnt[dst[e]], 1);
        g_epos[e] = p;
    }
}

// ---- multi-block exclusive scan, phase 1: per-block scan + block totals ----
__global__ void k_scan1()
{
    __shared__ int wsum[8];
    int tid = threadIdx.x, lane = tid & 31, wid = tid >> 5;
    int qi = blockIdx.x * 256 + tid;

    int4 v = make_int4(0, 0, 0, 0);
    if (qi < NQ) v = ((const int4*)g_cnt)[qi];
    int t0 = v.x, t1 = t0 + v.y, t2 = t1 + v.z, t3 = t2 + v.w;

    int inc = t3;
    #pragma unroll
    for (int d = 1; d < 32; d <<= 1) {
        int t = __shfl_up_sync(0xffffffffu, inc, d);
        if (lane >= d) inc += t;
    }
    if (lane == 31) wsum[wid] = inc;
    __syncthreads();
    if (wid == 0 && lane < 8) {
        int w = wsum[lane];
        int wi = w;
        #pragma unroll
        for (int d = 1; d < 8; d <<= 1) {
            int t = __shfl_up_sync(0x000000ffu, wi, d);
            if (lane >= d) wi += t;
        }
        wsum[lane] = wi - w;       // exclusive prefix of warp sums
    }
    __syncthreads();

    int excl = wsum[wid] + inc - t3;   // block-local exclusive prefix
    if (qi < NQ) {
        ((int4*)g_off)[qi] = make_int4(excl, excl + t0, excl + t1, excl + t2);
        ((float4*)g_dinv)[qi] = make_float4(rsqrtf((float)(v.x + 1)),
                                            rsqrtf((float)(v.y + 1)),
                                            rsqrtf((float)(v.z + 1)),
                                            rsqrtf((float)(v.w + 1)));
    }
    if (tid == 255) g_bsum[blockIdx.x] = wsum[wid] + inc;   // block total
}

// phase 2: exclusive scan of SCAN_BLOCKS (<=64) block totals
__global__ void k_scan2()
{
    __shared__ int w0tot;
    int tid = threadIdx.x;
    int v = (tid < SCAN_BLOCKS) ? g_bsum[tid] : 0;
    int inc = v;
    int lane = tid & 31;
    #pragma unroll
    for (int d = 1; d < 32; d <<= 1) {
        int t = __shfl_up_sync(0xffffffffu, inc, d);
        if (lane >= d) inc += t;
    }
    if (tid == 31) w0tot = inc;
    __syncthreads();
    int excl = inc - v + ((tid >= 32) ? w0tot : 0);
    if (tid < SCAN_BLOCKS) g_bsum[tid] = excl;
}

// phase 3: add block offsets, produce final g_off
__global__ void k_scan3()
{
    int tid = threadIdx.x;
    int qi = blockIdx.x * 256 + tid;
    if (qi < NQ) {
        int add = g_bsum[blockIdx.x];
        int4 o = ((int4*)g_off)[qi];
        o.x += add; o.y += add; o.z += add; o.w += add;
        ((int4*)g_off)[qi] = o;
    }
    if (blockIdx.x == 0 && tid == 0) g_off[NN] = NE;   // total = NE
}

// 1 edge/thread, atomic-free: slot = g_off[dst] + g_epos[e].
__global__ void k_fill(const int* __restrict__ src,
                       const int* __restrict__ dst)
{
    int e = blockIdx.x * blockDim.x + threadIdx.x;
    if (e < NE) {
        int s = src[e];
        int d = dst[e];
        int p = g_off[d] + g_epos[e];
        g_edge[p] = make_int2(s, __float_as_int(g_dinv[s] * g_dinv[d]));
    }
}

// ---------------- GEMM: g_hA = Xin @ W  (Xin: [NN,96], W: [96,96]) ---------
__global__ __launch_bounds__(384) void k_gemm(const float* __restrict__ Xext,
                                              const float* __restrict__ W)
{
    __shared__ float Ws[96 * 96];
    __shared__ float Xs[96 * 64];
    int tid = threadIdx.x;

    const float* X = Xext ? Xext : g_hB;

    const float4* W4  = (const float4*)W;
    float4*       Ws4 = (float4*)Ws;
    #pragma unroll
    for (int i = 0; i < 6; i++) Ws4[tid + i * 384] = W4[tid + i * 384];

    int row0 = blockIdx.x * 64;
    #pragma unroll
    for (int i = 0; i < 4; i++) {
        int idx = tid + i * 384;        // 0..1535 -> (m, q)
        int m = idx / 24, q = idx % 24;
        int row = row0 + m;
        float4 v = make_float4(0.f, 0.f, 0.f, 0.f);
        if (row < NN) v = ((const float4*)(X + (size_t)row * 96))[q];
        Xs[(q * 4 + 0) * 64 + m] = v.x;
        Xs[(q * 4 + 1) * 64 + m] = v.y;
        Xs[(q * 4 + 2) * 64 + m] = v.z;
        Xs[(q * 4 + 3) * 64 + m] = v.w;
    }
    __syncthreads();

    int tn = tid % 24;      // 4-col group
    int tm = tid / 24;      // 4-row group

    unsigned long long acc[4][2];
    unsigned long long z = pk2(0.f, 0.f);
    #pragma unroll
    for (int i = 0; i < 4; i++) { acc[i][0] = z; acc[i][1] = z; }

    #pragma unroll 4
    for (int k = 0; k < 96; k++) {
        float4 a4 = *(const float4*)&Xs[k * 64 + tm * 4];
        float4 b4 = *(const float4*)&Ws[k * 96 + tn * 4];
        unsigned long long b01 = pk2(b4.x, b4.y);
        unsigned long long b23 = pk2(b4.z, b4.w);
        unsigned long long aa;
        aa = pk2(a4.x, a4.x); ffma2(acc[0][0], aa, b01); ffma2(acc[0][1], aa, b23);
        aa = pk2(a4.y, a4.y); ffma2(acc[1][0], aa, b01); ffma2(acc[1][1], aa, b23);
        aa = pk2(a4.z, a4.z); ffma2(acc[2][0], aa, b01); ffma2(acc[2][1], aa, b23);
        aa = pk2(a4.w, a4.w); ffma2(acc[3][0], aa, b01); ffma2(acc[3][1], aa, b23);
    }

    #pragma unroll
    for (int i = 0; i < 4; i++) {
        int row = row0 + tm * 4 + i;
        if (row < NN) {
            float r0, r1, r2, r3;
            upk2(acc[i][0], r0, r1);
            upk2(acc[i][1], r2, r3);
            *(float4*)&g_hA[(size_t)row * 96 + tn * 4] = make_float4(r0, r1, r2, r3);
        }
    }
}

// ---------------- aggregation core (one warp per node) ---------------------
// Main loop unrolled x8 with 8 direct broadcast meta loads (NO shfl) + 24
// independent H-row loads per iteration; 4-edge and scalar tails.
__device__ __forceinline__ void agg_node(int node, int lane,
                                         const float* __restrict__ bias,
                                         float& a0, float& a1, float& a2)
{
    const float* H = g_hA;

    float di = g_dinv[node];
    float wself = di * di;
    const float* hr = H + (size_t)node * 96;
    a0 = wself * hr[lane];
    a1 = wself * hr[lane + 32];
    a2 = wself * hr[lane + 64];

    int j  = g_off[node];
    int e1 = g_off[node + 1];

    for (; j + 7 < e1; j += 8) {
        int2 e0 = g_edge[j];
        int2 e1m = g_edge[j + 1];
        int2 e2 = g_edge[j + 2];
        int2 e3 = g_edge[j + 3];
        int2 e4 = g_edge[j + 4];
        int2 e5 = g_edge[j + 5];
        int2 e6 = g_edge[j + 6];
        int2 e7 = g_edge[j + 7];
        const float* h0 = H + (size_t)e0.x  * 96;
        const float* h1 = H + (size_t)e1m.x * 96;
        const float* h2 = H + (size_t)e2.x  * 96;
        const float* h3 = H + (size_t)e3.x  * 96;
        const float* h4 = H + (size_t)e4.x  * 96;
        const float* h5 = H + (size_t)e5.x  * 96;
        const float* h6 = H + (size_t)e6.x  * 96;
        const float* h7 = H + (size_t)e7.x  * 96;
        float v00 = h0[lane], v01 = h0[lane + 32], v02 = h0[lane + 64];
        float v10 = h1[lane], v11 = h1[lane + 32], v12 = h1[lane + 64];
        float v20 = h2[lane], v21 = h2[lane + 32], v22 = h2[lane + 64];
        float v30 = h3[lane], v31 = h3[lane + 32], v32 = h3[lane + 64];
        float v40 = h4[lane], v41 = h4[lane + 32], v42 = h4[lane + 64];
        float v50 = h5[lane], v51 = h5[lane + 32], v52 = h5[lane + 64];
        float v60 = h6[lane], v61 = h6[lane + 32], v62 = h6[lane + 64];
        float v70 = h7[lane], v71 = h7[lane + 32], v72 = h7[lane + 64];
        float w0 = __int_as_float(e0.y);
        float w1 = __int_as_float(e1m.y);
        float w2 = __int_as_float(e2.y);
        float w3 = __int_as_float(e3.y);
        float w4 = __int_as_float(e4.y);
        float w5 = __int_as_float(e5.y);
        float w6 = __int_as_float(e6.y);
        float w7 = __int_as_float(e7.y);
        a0 += w0 * v00; a1 += w0 * v01; a2 += w0 * v02;
        a0 += w1 * v10; a1 += w1 * v11; a2 += w1 * v12;
        a0 += w2 * v20; a1 += w2 * v21; a2 += w2 * v22;
        a0 += w3 * v30; a1 += w3 * v31; a2 += w3 * v32;
        a0 += w4 * v40; a1 += w4 * v41; a2 += w4 * v42;
        a0 += w5 * v50; a1 += w5 * v51; a2 += w5 * v52;
        a0 += w6 * v60; a1 += w6 * v61; a2 += w6 * v62;
        a0 += w7 * v70; a1 += w7 * v71; a2 += w7 * v72;
    }
    for (; j + 3 < e1; j += 4) {
        int2 eA = g_edge[j];
        int2 eB = g_edge[j + 1];
        int2 eC = g_edge[j + 2];
        int2 eD = g_edge[j + 3];
        const float* ha = H + (size_t)eA.x * 96;
        const float* hb = H + (size_t)eB.x * 96;
        const float* hc = H + (size_t)eC.x * 96;
        const float* hd = H + (size_t)eD.x * 96;
        float wA = __int_as_float(eA.y);
        float wB = __int_as_float(eB.y);
        float wC = __int_as_float(eC.y);
        float wD = __int_as_float(eD.y);
        float vA0 = ha[lane], vA1 = ha[lane + 32], vA2 = ha[lane + 64];
        float vB0 = hb[lane], vB1 = hb[lane + 32], vB2 = hb[lane + 64];
        float vC0 = hc[lane], vC1 = hc[lane + 32], vC2 = hc[lane + 64];
        float vD0 = hd[lane], vD1 = hd[lane + 32], vD2 = hd[lane + 64];
        a0 += wA * vA0; a1 += wA * vA1; a2 += wA * vA2;
        a0 += wB * vB0; a1 += wB * vB1; a2 += wB * vB2;
        a0 += wC * vC0; a1 += wC * vC1; a2 += wC * vC2;
        a0 += wD * vD0; a1 += wD * vD1; a2 += wD * vD2;
    }
    for (; j < e1; j++) {
        int2 eA = g_edge[j];
        const float* ha = H + (size_t)eA.x * 96;
        float wA = __int_as_float(eA.y);
        a0 += wA * ha[lane];
        a1 += wA * ha[lane + 32];
        a2 += wA * ha[lane + 64];
    }
    a0 = fmaxf(a0 + bias[lane],      0.f);
    a1 = fmaxf(a1 + bias[lane + 32], 0.f);
    a2 = fmaxf(a2 + bias[lane + 64], 0.f);
}

// layers 0,1: g_hB = relu(A_hat @ g_hA + b)
__global__ __launch_bounds__(256) void k_agg(const float* __restrict__ bias)
{
    int node = blockIdx.x * 8 + threadIdx.y;
    if (node >= NN) return;
    int lane = threadIdx.x;

    float a0, a1, a2;
    agg_node(node, lane, bias, a0, a1, a2);

    size_t o = (size_t)node * 96 + lane;
    g_hB[o]      = a0;
    g_hB[o + 32] = a1;
    g_hB[o + 64] = a2;
}

// layer 2 + FC head fused: out = relu(A_hat @ g_hA + b2) @ Wfc + bfc
__global__ __launch_bounds__(256) void k_agg_fc(const float* __restrict__ bias,
                                                const float* __restrict__ Wfc,
                                                const float* __restrict__ bfc,
                                                float* __restrict__ Out)
{
    int node = blockIdx.x * 8 + threadIdx.y;
    if (node >= NN) return;
    int lane = threadIdx.x;

    float a0, a1, a2;
    agg_node(node, lane, bias, a0, a1, a2);

    const float4* W4 = (const float4*)Wfc;         // [96] rows of float4
    float4 w0 = W4[lane];
    float4 w1 = W4[lane + 32];
    float4 w2 = W4[lane + 64];

    float o0 = a0 * w0.x + a1 * w1.x + a2 * w2.x;
    float o1 = a0 * w0.y + a1 * w1.y + a2 * w2.y;
    float o2 = a0 * w0.z + a1 * w1.z + a2 * w2.z;
    float o3 = a0 * w0.w + a1 * w1.w + a2 * w2.w;

    #pragma unroll
    for (int d = 16; d > 0; d >>= 1) {
        o0 += __shfl_xor_sync(0xffffffffu, o0, d);
        o1 += __shfl_xor_sync(0xffffffffu, o1, d);
        o2 += __shfl_xor_sync(0xffffffffu, o2, d);
        o3 += __shfl_xor_sync(0xffffffffu, o3, d);
    }
    if (lane == 0) {
        const float4 bf = *(const float4*)bfc;
        *(float4*)&Out[(size_t)node * 4] =
            make_float4(o0 + bf.x, o1 + bf.y, o2 + bf.z, o3 + bf.w);
    }
}

// ---------------- launch ----------------------------------------------------
extern "C" void kernel_launch(void* const* d_in, const int* in_sizes, int n_in,
                              void* d_out, int out_size)
{
    const float* x    = (const float*)d_in[0];
    const int*   ei   = (const int*)d_in[1];     // int32, [2, NE]
    const float* W0   = (const float*)d_in[2];
    const float* b0   = (const float*)d_in[3];
    const float* W1   = (const float*)d_in[4];
    const float* b1   = (const float*)d_in[5];
    const float* W2   = (const float*)d_in[6];
    const float* b2   = (const float*)d_in[7];
    const float* Wfc  = (const float*)d_in[8];
    const float* bfc  = (const float*)d_in[9];
    float*       out  = (float*)d_out;

    const int* srcE = ei;
    const int* dstE = ei + NE;

    // one-time resources (no device memory; work per call is identical)
    static cudaStream_t s2 = nullptr;
    static cudaEvent_t ev_fork = nullptr, ev_join = nullptr;
    if (!s2) {
        cudaStreamCreateWithFlags(&s2, cudaStreamNonBlocking);
        cudaEventCreateWithFlags(&ev_fork, cudaEventDisableTiming);
        cudaEventCreateWithFlags(&ev_join, cudaEventDisableTiming);
    }

    int gb_zero = (NQ + 255) / 256;
    int gb_e    = (NE + 255) / 256;
    int gemm_blocks = (NN + 63) / 64;
    dim3 agg_block(32, 8);
    int agg_blocks = (NN + 7) / 8;

    // fork: gemm0 (x @ W0 -> hA) runs concurrently with graph preprocessing
    cudaEventRecord(ev_fork, 0);
    cudaStreamWaitEvent(s2, ev_fork, 0);
    k_gemm<<<gemm_blocks, 384, 0, s2>>>(x, W0);
    cudaEventRecord(ev_join, s2);

    // main stream: graph preprocessing chain
    k_zero <<<gb_zero, 256>>>();
    k_hist <<<gb_e, 256>>>(dstE);
    k_scan1<<<SCAN_BLOCKS, 256>>>();
    k_scan2<<<1, 64>>>();
    k_scan3<<<SCAN_BLOCKS, 256>>>();
    k_fill <<<gb_e, 256>>>(srcE, dstE);

    // join: agg0 needs both hA (gemm0) and the CSR
    cudaStreamWaitEvent(0, ev_join, 0);
    k_agg<<<agg_blocks, agg_block>>>(b0);

    // layer 1
    k_gemm<<<gemm_blocks, 384>>>(nullptr, W1);
    k_agg <<<agg_blocks, agg_block>>>(b1);
    // layer 2 + FC head fused
    k_gemm<<<gemm_blocks, 384>>>(nullptr, W2);
    k_agg_fc<<<agg_blocks, agg_block>>>(b2, Wfc, bfc, out);

    (void)in_sizes; (void)n_in; (void)out_size;
}